// round 11
// baseline (speedup 1.0000x reference)
#include <cuda_runtime.h>
#include <cstdint>

// Problem constants
#define B   16
#define NC  31
#define NO  3
#define NX  256
#define NY  256
#define NLOC 7533          // 3*31*81
#define NGRP 93            // 3*31

// Tiling
#define TILE_H 16
#define TILE_W 128
#define THR    128         // 8 thread-rows x 16 thread-cols
#define TH     2           // output rows per thread
#define HALF   64          // lane split: f32x2 lanes are cols (w, w+64)
#define SROWS  24          // TILE_H + 8 halo
#define SP2    72          // float2 pairs per smem row = 36 16B chunks
#define STILE  (SROWS * SP2)   // 1728 pairs
#define NIT    14              // ceil(1728/128)

__device__ float2 g_w2[NLOC];  // relu'd weights duplicated into both lanes
__device__ int    g_off[NGRP]; // per (o,c) column offset cx-8 in [-4,4]

__device__ __forceinline__ void fma2(unsigned long long& acc,
                                     unsigned long long a,
                                     unsigned long long b) {
    asm("fma.rn.f32x2 %0, %1, %2, %0;" : "+l"(acc) : "l"(a), "l"(b));
}
__device__ __forceinline__ void unpk2(unsigned long long v, float& lo, float& hi) {
    asm("mov.b64 {%0, %1}, %2;" : "=f"(lo), "=f"(hi) : "l"(v));
}

// chunk swizzle: break the 32B-stride / 128B-period 4-way conflict
__device__ __host__ __forceinline__ int swz(int c) {
    return c ^ ((c >> 3) & 1);
}

// ---- prep: relu + duplicate weights, extract per-group column offsets ----
__global__ void prep_kernel(const float* __restrict__ vk,
                            const int* __restrict__ loc) {
    int t = blockIdx.x * blockDim.x + threadIdx.x;
    if (t < NLOC) {
        float w = fmaxf(vk[t], 0.0f);
        g_w2[t] = make_float2(w, w);
    }
    if (t < NGRP) {
        int loc0 = loc[t * 81];          // first entry: (dy=-4, dx=-4)
        g_off[t] = (loc0 % 17) - 4;      // cx - 8
    }
}

// stage channel c's tile + weights into the given buffers
__device__ __forceinline__ void stage_channel(
    const float* __restrict__ x, int b, int o, int c,
    int y0, int x0, int tid,
    float2* __restrict__ buf, float2* __restrict__ wbuf)
{
    const int oc  = g_off[o * NC + c];
    const float* __restrict__ xc = x + ((size_t)(b * NC + c)) * (NX * NY);
    const int gx0 = x0 - 4 + oc;

    if (tid < 81)
        wbuf[tid] = __ldg(&g_w2[(o * NC + c) * 81 + tid]);

    #pragma unroll
    for (int k = 0; k < NIT; k++) {
        int i = tid + k * THR;
        if (i < STILE) {
            int row = i / SP2;
            int p   = i - row * SP2;
            int gy  = y0 + row - 4;
            int gxa = gx0 + p;
            int gxb = gxa + HALF;
            float va = 0.0f, vb = 0.0f;
            if ((unsigned)gy < (unsigned)NX) {
                const float* rowp = xc + gy * NY;
                if ((unsigned)gxa < (unsigned)NY) va = __ldg(rowp + gxa);
                if ((unsigned)gxb < (unsigned)NY) vb = __ldg(rowp + gxb);
            }
            buf[row * SP2 + swz(p >> 1) * 2 + (p & 1)] = make_float2(va, vb);
        }
    }
}

// ---- main conv: one block = (b, o, 16x128 tile), pipelined channels ----
__global__ __launch_bounds__(THR)
void conv_kernel(const float* __restrict__ x, float* __restrict__ out) {
    __shared__ __align__(16) float2 s2[2][STILE]; // double-buffered tiles
    __shared__ __align__(16) float2 ws[2][81];    // double-buffered weights

    const int bz = blockIdx.z;
    const int b  = bz / NO;
    const int o  = bz % NO;
    const int y0 = blockIdx.y * TILE_H;
    const int x0 = blockIdx.x * TILE_W;

    const int tid = threadIdx.x;
    const int twi = tid & 15;        // 0..15
    const int thi = tid >> 4;        // 0..7
    const int h0  = thi * TH;        // tile-local out row base (0..14)
    const int w0p = twi * 4;         // logical pair base

    // per-thread swizzled chunk byte-offsets within a row (6 chunks)
    int coff[6];
    #pragma unroll
    for (int k = 0; k < 6; k++)
        coff[k] = swz(twi * 2 + k) * 16;

    unsigned long long acc[TH][4];
    #pragma unroll
    for (int i = 0; i < TH; i++)
        #pragma unroll
        for (int j = 0; j < 4; j++) acc[i][j] = 0ULL;

    // prologue: stage channel 0
    stage_channel(x, b, o, 0, y0, x0, tid, s2[0], ws[0]);
    __syncthreads();

    for (int c = 0; c < NC; c++) {
        const int cur = c & 1;
        const int nxt = cur ^ 1;

        // prefetch next channel while computing this one
        if (c + 1 < NC)
            stage_channel(x, b, o, c + 1, y0, x0, tid, s2[nxt], ws[nxt]);

        const unsigned long long* __restrict__ wsu =
            (const unsigned long long*)ws[cur];
        const float2* __restrict__ sb = s2[cur];

        #pragma unroll
        for (int r = 0; r < TH + 8; r++) {       // 10 input rows
            const char* rb = (const char*)&sb[(h0 + r) * SP2];
            unsigned long long q[12];
            #pragma unroll
            for (int k = 0; k < 6; k++) {
                ulonglong2 u = *(const ulonglong2*)(rb + coff[k]);
                q[2 * k]     = u.x;
                q[2 * k + 1] = u.y;
            }

            #pragma unroll
            for (int hh = 0; hh < TH; hh++) {
                const int dyi = r - hh;          // dy + 4
                if (dyi < 0 || dyi > 8) continue;
                const unsigned long long* __restrict__ wr = wsu + dyi * 9;
                #pragma unroll
                for (int dx = 0; dx < 9; dx++) {
                    unsigned long long wp = wr[dx];   // LDS.64 broadcast
                    fma2(acc[hh][0], wp, q[dx + 0]);
                    fma2(acc[hh][1], wp, q[dx + 1]);
                    fma2(acc[hh][2], wp, q[dx + 2]);
                    fma2(acc[hh][3], wp, q[dx + 3]);
                }
            }
        }
        __syncthreads();   // staging of c+1 done; compute of c done
    }

    // write: lane0 -> cols x0+w0.., lane1 -> cols x0+64+w0..
    float* __restrict__ op =
        out + (((size_t)(b * NO + o)) * NX + (y0 + h0)) * NY + x0 + w0p;
    #pragma unroll
    for (int hh = 0; hh < TH; hh++) {
        float a0, b0, a1, b1, a2, b2, a3, b3;
        unpk2(acc[hh][0], a0, b0);
        unpk2(acc[hh][1], a1, b1);
        unpk2(acc[hh][2], a2, b2);
        unpk2(acc[hh][3], a3, b3);
        *(float4*)(op + hh * NY)        = make_float4(a0, a1, a2, a3);
        *(float4*)(op + hh * NY + HALF) = make_float4(b0, b1, b2, b3);
    }
}

extern "C" void kernel_launch(void* const* d_in, const int* in_sizes, int n_in,
                              void* d_out, int out_size) {
    const float* x   = (const float*)d_in[0];
    const float* vk  = (const float*)d_in[1];
    const int*   loc = (const int*)d_in[2];
    float* out = (float*)d_out;

    prep_kernel<<<30, 256>>>(vk, loc);

    dim3 grid(NY / TILE_W, NX / TILE_H, B * NO);   // (2, 16, 48)
    conv_kernel<<<grid, THR>>>(x, out);
}

// round 13
// speedup vs baseline: 1.4920x; 1.4920x over previous
#include <cuda_runtime.h>
#include <cstdint>

// Problem constants
#define B   16
#define NC  31
#define NO  3
#define NX  256
#define NY  256
#define NLOC 7533          // 3*31*81
#define NGRP 93            // 3*31

// Tiling
#define TILE_H 16
#define TILE_W 128
#define THR    128         // 8 thread-rows x 16 thread-cols
#define TH     2           // output rows per thread
#define HALF   64          // lane split: f32x2 lanes are cols (w, w+64)
#define SROWS  24          // TILE_H + 8 halo
#define SP2    72          // float2 pairs per smem row = 36 16B chunks
#define STILE  (SROWS * SP2)   // 1728 pairs
#define NIT    14              // ceil(1728/128)

__device__ float2 g_w2[NLOC];  // relu'd weights duplicated into both lanes
__device__ int    g_off[NGRP]; // per (o,c) column offset cx-8 in [-4,4]

__device__ __forceinline__ void fma2(unsigned long long& acc,
                                     unsigned long long a,
                                     unsigned long long b) {
    asm("fma.rn.f32x2 %0, %1, %2, %0;" : "+l"(acc) : "l"(a), "l"(b));
}
__device__ __forceinline__ void unpk2(unsigned long long v, float& lo, float& hi) {
    asm("mov.b64 {%0, %1}, %2;" : "=f"(lo), "=f"(hi) : "l"(v));
}

// chunk swizzle: spread 32B-stride accesses across all banks
__device__ __host__ __forceinline__ int swz(int c) {
    return c ^ ((c >> 3) & 1);
}

// 4-byte cp.async with zero-fill (src_size 0 -> zfill)
__device__ __forceinline__ void cpa4(uint32_t dst, const float* src, int sz) {
    asm volatile("cp.async.ca.shared.global [%0], [%1], 4, %2;"
                 :: "r"(dst), "l"(src), "r"(sz));
}
// 8-byte cp.async (weights, always in bounds)
__device__ __forceinline__ void cpa8(uint32_t dst, const float2* src) {
    asm volatile("cp.async.ca.shared.global [%0], [%1], 8;"
                 :: "r"(dst), "l"(src));
}
__device__ __forceinline__ void cpa_commit() {
    asm volatile("cp.async.commit_group;");
}
__device__ __forceinline__ void cpa_wait0() {
    asm volatile("cp.async.wait_group 0;");
}

// ---- prep: relu + duplicate weights, extract per-group column offsets ----
__global__ void prep_kernel(const float* __restrict__ vk,
                            const int* __restrict__ loc) {
    int t = blockIdx.x * blockDim.x + threadIdx.x;
    if (t < NLOC) {
        float w = fmaxf(vk[t], 0.0f);
        g_w2[t] = make_float2(w, w);
    }
    if (t < NGRP) {
        int loc0 = loc[t * 81];          // first entry: (dy=-4, dx=-4)
        g_off[t] = (loc0 % 17) - 4;      // cx - 8
    }
}

// stage channel c's tile + weights into smem via cp.async (no registers)
__device__ __forceinline__ void stage_channel(
    const float* __restrict__ x, int b, int o, int c,
    int y0, int x0, int tid,
    uint32_t buf_sa, uint32_t wbuf_sa)
{
    const int oc  = g_off[o * NC + c];
    const float* __restrict__ xc = x + ((size_t)(b * NC + c)) * (NX * NY);
    const int gx0 = x0 - 4 + oc;

    if (tid < 81)
        cpa8(wbuf_sa + tid * 8, &g_w2[(o * NC + c) * 81 + tid]);

    #pragma unroll
    for (int k = 0; k < NIT; k++) {
        int i = tid + k * THR;
        if (i < STILE) {
            int row = i / SP2;
            int p   = i - row * SP2;
            int gy  = y0 + row - 4;
            int gxa = gx0 + p;
            int gxb = gxa + HALF;
            bool okr = (unsigned)gy < (unsigned)NX;
            int sza = (okr && (unsigned)gxa < (unsigned)NY) ? 4 : 0;
            int szb = (okr && (unsigned)gxb < (unsigned)NY) ? 4 : 0;
            const float* rowp = xc + (okr ? gy * NY : 0);
            const float* pa = rowp + (sza ? gxa : 0);
            const float* pb = rowp + (szb ? gxb : 0);
            uint32_t dst = buf_sa +
                (row * SP2 + swz(p >> 1) * 2 + (p & 1)) * 8;
            cpa4(dst,     pa, sza);
            cpa4(dst + 4, pb, szb);
        }
    }
}

// ---- main conv: one block = (b, o, 16x128 tile), cp.async pipelined ----
__global__ __launch_bounds__(THR)
void conv_kernel(const float* __restrict__ x, float* __restrict__ out) {
    __shared__ __align__(16) float2 s2[2][STILE]; // double-buffered tiles
    __shared__ __align__(16) float2 ws[2][81];    // double-buffered weights

    const int bz = blockIdx.z;
    const int b  = bz / NO;
    const int o  = bz % NO;
    const int y0 = blockIdx.y * TILE_H;
    const int x0 = blockIdx.x * TILE_W;

    const int tid = threadIdx.x;
    const int twi = tid & 15;        // 0..15
    const int thi = tid >> 4;        // 0..7
    const int h0  = thi * TH;        // tile-local out row base (0..14)
    const int w0p = twi * 4;         // logical pair base

    const uint32_t s2_sa = (uint32_t)__cvta_generic_to_shared(&s2[0][0]);
    const uint32_t ws_sa = (uint32_t)__cvta_generic_to_shared(&ws[0][0]);

    // per-thread swizzled chunk byte-offsets within a row (6 chunks)
    int coff[6];
    #pragma unroll
    for (int k = 0; k < 6; k++)
        coff[k] = swz(twi * 2 + k) * 16;

    unsigned long long acc[TH][4];
    #pragma unroll
    for (int i = 0; i < TH; i++)
        #pragma unroll
        for (int j = 0; j < 4; j++) acc[i][j] = 0ULL;

    // prologue: stage channel 0
    stage_channel(x, b, o, 0, y0, x0, tid, s2_sa, ws_sa);
    cpa_commit();
    cpa_wait0();
    __syncthreads();

    for (int c = 0; c < NC; c++) {
        const int cur = c & 1;
        const int nxt = cur ^ 1;

        // prefetch next channel into the other buffer (register-free)
        if (c + 1 < NC) {
            stage_channel(x, b, o, c + 1, y0, x0, tid,
                          s2_sa + nxt * (STILE * 8),
                          ws_sa + nxt * (81 * 8));
            cpa_commit();
        }

        const unsigned long long* __restrict__ wsu =
            (const unsigned long long*)ws[cur];
        const float2* __restrict__ sb = s2[cur];

        #pragma unroll
        for (int r = 0; r < TH + 8; r++) {       // 10 input rows
            const char* rb = (const char*)&sb[(h0 + r) * SP2];
            unsigned long long q[12];
            #pragma unroll
            for (int k = 0; k < 6; k++) {
                ulonglong2 u = *(const ulonglong2*)(rb + coff[k]);
                q[2 * k]     = u.x;
                q[2 * k + 1] = u.y;
            }

            #pragma unroll
            for (int hh = 0; hh < TH; hh++) {
                const int dyi = r - hh;          // dy + 4
                if (dyi < 0 || dyi > 8) continue;
                const unsigned long long* __restrict__ wr = wsu + dyi * 9;
                #pragma unroll
                for (int dx = 0; dx < 9; dx++) {
                    unsigned long long wp = wr[dx];   // LDS.64 broadcast
                    fma2(acc[hh][0], wp, q[dx + 0]);
                    fma2(acc[hh][1], wp, q[dx + 1]);
                    fma2(acc[hh][2], wp, q[dx + 2]);
                    fma2(acc[hh][3], wp, q[dx + 3]);
                }
            }
        }

        cpa_wait0();       // next channel's staging has landed
        __syncthreads();   // all warps done reading cur + staging visible
    }

    // write: lane0 -> cols x0+w0.., lane1 -> cols x0+64+w0..
    float* __restrict__ op =
        out + (((size_t)(b * NO + o)) * NX + (y0 + h0)) * NY + x0 + w0p;
    #pragma unroll
    for (int hh = 0; hh < TH; hh++) {
        float a0, b0, a1, b1, a2, b2, a3, b3;
        unpk2(acc[hh][0], a0, b0);
        unpk2(acc[hh][1], a1, b1);
        unpk2(acc[hh][2], a2, b2);
        unpk2(acc[hh][3], a3, b3);
        *(float4*)(op + hh * NY)        = make_float4(a0, a1, a2, a3);
        *(float4*)(op + hh * NY + HALF) = make_float4(b0, b1, b2, b3);
    }
}

extern "C" void kernel_launch(void* const* d_in, const int* in_sizes, int n_in,
                              void* d_out, int out_size) {
    const float* x   = (const float*)d_in[0];
    const float* vk  = (const float*)d_in[1];
    const int*   loc = (const int*)d_in[2];
    float* out = (float*)d_out;

    prep_kernel<<<30, 256>>>(vk, loc);

    dim3 grid(NY / TILE_W, NX / TILE_H, B * NO);   // (2, 16, 48)
    conv_kernel<<<grid, THR>>>(x, out);
}